// round 2
// baseline (speedup 1.0000x reference)
#include <cuda_runtime.h>
#include <math.h>

// Problem shapes (fixed by the dataset)
#define T_    4096            // tokens = B*S
#define D_    1024            // model dim
#define H_    512             // expert inter dim
#define E_    32              // experts
#define TOPK_ 4
#define CAP_  2048            // CAP_FACTOR * P / E = 4*16384/32
#define HS_   1024            // shared inter dim
#define P_    (T_*TOPK_)

// ---------------- scratch (device globals; no allocations allowed) ----------
__device__ int   g_topk_idx[P_];
__device__ float g_topk_w[P_];
__device__ int   g_counts[E_];
__device__ int   g_rows_token[E_*CAP_];
__device__ float g_slot_w[E_*CAP_];
__device__ float g_Gbuf[(size_t)E_*CAP_*H_];   // 134 MB: silu(xW1)*xW3 per expert slot
__device__ float g_Gs[(size_t)T_*HS_];         // 16 MB: shared-expert hidden

// ---------------- gating: softmax + top-4 ----------------------------------
__global__ __launch_bounds__(256) void gate_kernel(const float* __restrict__ x,
                                                   const float* __restrict__ Wg)
{
    __shared__ float xs[D_];
    __shared__ float red[8][E_];
    __shared__ float probs[E_];
    int t   = blockIdx.x;
    int tid = threadIdx.x;

    ((float4*)xs)[tid] = ((const float4*)(x + (size_t)t * D_))[tid];
    __syncthreads();

    int e = tid & 31, seg = tid >> 5;
    int k0 = seg * (D_/8);
    float acc = 0.f;
    #pragma unroll 8
    for (int k = 0; k < D_/8; ++k)
        acc = fmaf(xs[k0 + k], Wg[(size_t)(k0 + k) * E_ + e], acc);
    red[seg][e] = acc;
    __syncthreads();

    if (tid < E_) {
        float s = 0.f;
        #pragma unroll
        for (int i = 0; i < 8; ++i) s += red[i][tid];
        float m = s;
        #pragma unroll
        for (int o = 16; o > 0; o >>= 1) m = fmaxf(m, __shfl_xor_sync(0xffffffffu, m, o));
        float p = expf(s - m);
        float sum = p;
        #pragma unroll
        for (int o = 16; o > 0; o >>= 1) sum += __shfl_xor_sync(0xffffffffu, sum, o);
        probs[tid] = p / sum;
    }
    __syncthreads();

    if (tid == 0) {
        bool used[E_];
        #pragma unroll
        for (int i = 0; i < E_; ++i) used[i] = false;
        for (int k = 0; k < TOPK_; ++k) {
            float best = -1.f; int bi = 0;
            for (int i = 0; i < E_; ++i)
                if (!used[i] && probs[i] > best) { best = probs[i]; bi = i; }
            used[bi] = true;
            g_topk_idx[t * TOPK_ + k] = bi;
            g_topk_w  [t * TOPK_ + k] = best;
        }
    }
}

// ---------------- dispatch ---------------------------------------------------
__global__ void zero_counts_kernel() {
    if (threadIdx.x < E_) g_counts[threadIdx.x] = 0;
}

__global__ void dispatch_kernel() {
    int p = blockIdx.x * blockDim.x + threadIdx.x;
    if (p >= P_) return;
    int e   = g_topk_idx[p];
    int tok = p >> 2;
    int pos = atomicAdd(&g_counts[e], 1);
    if (pos < CAP_) {
        int slot = e * CAP_ + pos;
        g_rows_token[slot] = tok;
        g_slot_w[slot]     = g_topk_w[p];
    }
}

// ---------------- expert GEMM1: G = silu(A@W1) * (A@W3), A gathered ---------
__global__ __launch_bounds__(256) void expert_gemm1(const float* __restrict__ x,
                                                    const float* __restrict__ W1,
                                                    const float* __restrict__ W3)
{
    int e  = blockIdx.z;
    int nc = min(g_counts[e], CAP_);
    int r0 = blockIdx.y * 64;
    if (r0 >= nc) return;
    int n0 = blockIdx.x * 64;

    __shared__ float AsT[16][68];
    __shared__ float B1s[16][64];
    __shared__ float B3s[16][64];

    int tid = threadIdx.x;
    int lr  = tid >> 2;
    int lk  = (tid & 3) << 2;
    int gr  = r0 + lr;
    int tok = (gr < nc) ? g_rows_token[e * CAP_ + gr] : 0;
    const float* arow = x + (size_t)tok * D_;

    int bk = tid >> 4;
    int bn = (tid & 15) << 2;
    const float* B1p = W1 + (size_t)e * D_ * H_ + (size_t)bk * H_ + n0 + bn;
    const float* B3p = W3 + (size_t)e * D_ * H_ + (size_t)bk * H_ + n0 + bn;

    float acc1[4][4] = {};
    float acc3[4][4] = {};
    int tx = tid & 15, ty = tid >> 4;

    for (int k0 = 0; k0 < D_; k0 += 16) {
        float4 av = *(const float4*)(arow + k0 + lk);
        AsT[lk+0][lr] = av.x; AsT[lk+1][lr] = av.y;
        AsT[lk+2][lr] = av.z; AsT[lk+3][lr] = av.w;
        *(float4*)&B1s[bk][bn] = *(const float4*)(B1p + (size_t)k0 * H_);
        *(float4*)&B3s[bk][bn] = *(const float4*)(B3p + (size_t)k0 * H_);
        __syncthreads();
        #pragma unroll
        for (int kk = 0; kk < 16; ++kk) {
            float4 a  = *(const float4*)&AsT[kk][ty << 2];
            float4 b1 = *(const float4*)&B1s[kk][tx << 2];
            float4 b3 = *(const float4*)&B3s[kk][tx << 2];
            float ar[4]  = {a.x, a.y, a.z, a.w};
            float b1r[4] = {b1.x, b1.y, b1.z, b1.w};
            float b3r[4] = {b3.x, b3.y, b3.z, b3.w};
            #pragma unroll
            for (int i = 0; i < 4; ++i)
                #pragma unroll
                for (int j = 0; j < 4; ++j) {
                    acc1[i][j] = fmaf(ar[i], b1r[j], acc1[i][j]);
                    acc3[i][j] = fmaf(ar[i], b3r[j], acc3[i][j]);
                }
        }
        __syncthreads();
    }

    float* G = g_Gbuf + ((size_t)e * CAP_ + r0) * H_;
    #pragma unroll
    for (int i = 0; i < 4; ++i) {
        int row = (ty << 2) + i;
        #pragma unroll
        for (int j = 0; j < 4; ++j) {
            float h1 = acc1[i][j];
            float g  = (h1 / (1.0f + expf(-h1))) * acc3[i][j];
            G[(size_t)row * H_ + n0 + (tx << 2) + j] = g;
        }
    }
}

// ---------------- expert GEMM2: y[tok] += w * (G @ W2) ----------------------
__global__ __launch_bounds__(256) void expert_gemm2(const float* __restrict__ W2,
                                                    float* __restrict__ y)
{
    int e  = blockIdx.z;
    int nc = min(g_counts[e], CAP_);
    int r0 = blockIdx.y * 64;
    if (r0 >= nc) return;
    int n0 = blockIdx.x * 64;

    __shared__ float AsT[16][68];
    __shared__ float Bs[16][64];

    int tid = threadIdx.x;
    int lr  = tid >> 2;
    int lk  = (tid & 3) << 2;
    const float* arow = g_Gbuf + ((size_t)e * CAP_ + r0 + lr) * H_;
    int bk = tid >> 4;
    int bn = (tid & 15) << 2;
    const float* Bp = W2 + (size_t)e * H_ * D_ + (size_t)bk * D_ + n0 + bn;

    float acc[4][4] = {};
    int tx = tid & 15, ty = tid >> 4;

    for (int k0 = 0; k0 < H_; k0 += 16) {
        float4 av = *(const float4*)(arow + k0 + lk);
        AsT[lk+0][lr] = av.x; AsT[lk+1][lr] = av.y;
        AsT[lk+2][lr] = av.z; AsT[lk+3][lr] = av.w;
        *(float4*)&Bs[bk][bn] = *(const float4*)(Bp + (size_t)k0 * D_);
        __syncthreads();
        #pragma unroll
        for (int kk = 0; kk < 16; ++kk) {
            float4 a = *(const float4*)&AsT[kk][ty << 2];
            float4 b = *(const float4*)&Bs[kk][tx << 2];
            float ar[4] = {a.x, a.y, a.z, a.w};
            float br[4] = {b.x, b.y, b.z, b.w};
            #pragma unroll
            for (int i = 0; i < 4; ++i)
                #pragma unroll
                for (int j = 0; j < 4; ++j)
                    acc[i][j] = fmaf(ar[i], br[j], acc[i][j]);
        }
        __syncthreads();
    }

    #pragma unroll
    for (int i = 0; i < 4; ++i) {
        int row = r0 + (ty << 2) + i;
        if (row < nc) {
            int slot = e * CAP_ + row;
            int tok  = g_rows_token[slot];
            float w  = g_slot_w[slot];
            float* yr = y + (size_t)tok * D_ + n0 + (tx << 2);
            #pragma unroll
            for (int j = 0; j < 4; ++j)
                atomicAdd(&yr[j], acc[i][j] * w);
        }
    }
}

// ---------------- shared expert GEMM1: Gs = silu(x@Ws1) * (x@Ws3) -----------
__global__ __launch_bounds__(256) void shared_gemm1(const float* __restrict__ x,
                                                    const float* __restrict__ Ws1,
                                                    const float* __restrict__ Ws3)
{
    int r0 = blockIdx.y * 64;
    int n0 = blockIdx.x * 64;

    __shared__ float AsT[16][68];
    __shared__ float B1s[16][64];
    __shared__ float B3s[16][64];

    int tid = threadIdx.x;
    int lr  = tid >> 2;
    int lk  = (tid & 3) << 2;
    const float* arow = x + (size_t)(r0 + lr) * D_;
    int bk = tid >> 4;
    int bn = (tid & 15) << 2;
    const float* B1p = Ws1 + (size_t)bk * HS_ + n0 + bn;
    const float* B3p = Ws3 + (size_t)bk * HS_ + n0 + bn;

    float acc1[4][4] = {};
    float acc3[4][4] = {};
    int tx = tid & 15, ty = tid >> 4;

    for (int k0 = 0; k0 < D_; k0 += 16) {
        float4 av = *(const float4*)(arow + k0 + lk);
        AsT[lk+0][lr] = av.x; AsT[lk+1][lr] = av.y;
        AsT[lk+2][lr] = av.z; AsT[lk+3][lr] = av.w;
        *(float4*)&B1s[bk][bn] = *(const float4*)(B1p + (size_t)k0 * HS_);
        *(float4*)&B3s[bk][bn] = *(const float4*)(B3p + (size_t)k0 * HS_);
        __syncthreads();
        #pragma unroll
        for (int kk = 0; kk < 16; ++kk) {
            float4 a  = *(const float4*)&AsT[kk][ty << 2];
            float4 b1 = *(const float4*)&B1s[kk][tx << 2];
            float4 b3 = *(const float4*)&B3s[kk][tx << 2];
            float ar[4]  = {a.x, a.y, a.z, a.w};
            float b1r[4] = {b1.x, b1.y, b1.z, b1.w};
            float b3r[4] = {b3.x, b3.y, b3.z, b3.w};
            #pragma unroll
            for (int i = 0; i < 4; ++i)
                #pragma unroll
                for (int j = 0; j < 4; ++j) {
                    acc1[i][j] = fmaf(ar[i], b1r[j], acc1[i][j]);
                    acc3[i][j] = fmaf(ar[i], b3r[j], acc3[i][j]);
                }
        }
        __syncthreads();
    }

    float* G = g_Gs + (size_t)r0 * HS_;
    #pragma unroll
    for (int i = 0; i < 4; ++i) {
        int row = (ty << 2) + i;
        #pragma unroll
        for (int j = 0; j < 4; ++j) {
            float h1 = acc1[i][j];
            float g  = (h1 / (1.0f + expf(-h1))) * acc3[i][j];
            G[(size_t)row * HS_ + n0 + (tx << 2) + j] = g;
        }
    }
}

// ---------------- shared expert GEMM2: y = Gs @ Ws2 (plain store) -----------
__global__ __launch_bounds__(256) void shared_gemm2(const float* __restrict__ Ws2,
                                                    float* __restrict__ y)
{
    int r0 = blockIdx.y * 64;
    int n0 = blockIdx.x * 64;

    __shared__ float AsT[16][68];
    __shared__ float Bs[16][64];

    int tid = threadIdx.x;
    int lr  = tid >> 2;
    int lk  = (tid & 3) << 2;
    const float* arow = g_Gs + (size_t)(r0 + lr) * HS_;
    int bk = tid >> 4;
    int bn = (tid & 15) << 2;
    const float* Bp = Ws2 + (size_t)bk * D_ + n0 + bn;

    float acc[4][4] = {};
    int tx = tid & 15, ty = tid >> 4;

    for (int k0 = 0; k0 < HS_; k0 += 16) {
        float4 av = *(const float4*)(arow + k0 + lk);
        AsT[lk+0][lr] = av.x; AsT[lk+1][lr] = av.y;
        AsT[lk+2][lr] = av.z; AsT[lk+3][lr] = av.w;
        *(float4*)&Bs[bk][bn] = *(const float4*)(Bp + (size_t)k0 * D_);
        __syncthreads();
        #pragma unroll
        for (int kk = 0; kk < 16; ++kk) {
            float4 a = *(const float4*)&AsT[kk][ty << 2];
            float4 b = *(const float4*)&Bs[kk][tx << 2];
            float ar[4] = {a.x, a.y, a.z, a.w};
            float br[4] = {b.x, b.y, b.z, b.w};
            #pragma unroll
            for (int i = 0; i < 4; ++i)
                #pragma unroll
                for (int j = 0; j < 4; ++j)
                    acc[i][j] = fmaf(ar[i], br[j], acc[i][j]);
        }
        __syncthreads();
    }

    #pragma unroll
    for (int i = 0; i < 4; ++i) {
        int row = r0 + (ty << 2) + i;
        float* yr = y + (size_t)row * D_ + n0 + (tx << 2);
        #pragma unroll
        for (int j = 0; j < 4; ++j)
            yr[j] = acc[i][j];
    }
}

// ---------------- launch -----------------------------------------------------
extern "C" void kernel_launch(void* const* d_in, const int* in_sizes, int n_in,
                              void* d_out, int out_size)
{
    const float* x   = (const float*)d_in[0];
    const float* Wg  = (const float*)d_in[1];
    const float* W1  = (const float*)d_in[2];
    const float* W2  = (const float*)d_in[3];
    const float* W3  = (const float*)d_in[4];
    const float* Ws1 = (const float*)d_in[5];
    const float* Ws2 = (const float*)d_in[6];
    const float* Ws3 = (const float*)d_in[7];
    float* y = (float*)d_out;

    gate_kernel<<<T_, 256>>>(x, Wg);
    zero_counts_kernel<<<1, 32>>>();
    dispatch_kernel<<<P_/256, 256>>>();

    // shared expert first: writes every y element (initializes output)
    shared_gemm1<<<dim3(HS_/64, T_/64), 256>>>(x, Ws1, Ws3);
    shared_gemm2<<<dim3(D_/64, T_/64), 256>>>(Ws2, y);

    // routed experts: accumulate into y with atomics (after shared write)
    expert_gemm1<<<dim3(H_/64, CAP_/64, E_), 256>>>(x, W1, W3);
    expert_gemm2<<<dim3(D_/64, CAP_/64, E_), 256>>>(W2, y);
}

// round 4
// speedup vs baseline: 2.2749x; 2.2749x over previous
#include <cuda_runtime.h>
#include <math.h>
#include <stdint.h>

// Problem shapes (fixed by the dataset)
#define T_    4096
#define D_    1024
#define H_    512
#define E_    32
#define TOPK_ 4
#define CAP_  2048
#define HS_   1024
#define P_    (T_*TOPK_)

// ---------------- scratch (device globals) ----------------------------------
__device__ int   g_topk_idx[P_];
__device__ float g_topk_w[P_];
__device__ float g_pair_wc[P_];                    // weight if dispatched, else 0
__device__ int   g_counts[E_];
__device__ int   g_rows_token[E_*CAP_];
__device__ int   g_slot_pair[E_*CAP_];
__device__ __align__(256) float g_Gs[(size_t)T_*HS_];        // shared hidden
__device__ __align__(256) float g_Gbuf[(size_t)E_*CAP_*H_];  // expert hidden
__device__ __align__(256) float g_Obuf[(size_t)P_*D_];       // per-pair outputs

// ---------------- helpers ----------------------------------------------------
__device__ __forceinline__ uint32_t smem_u32(const void* p) {
    uint32_t a;
    asm("{ .reg .u64 t; cvta.to.shared.u64 t, %1; cvt.u32.u64 %0, t; }"
        : "=r"(a) : "l"(p));
    return a;
}
__device__ __forceinline__ uint32_t rna_b(float v) {
    uint32_t o;
    asm("cvt.rna.tf32.f32 %0, %1;" : "=r"(o) : "f"(v));
    return o;
}
__device__ __forceinline__ void cp16(uint32_t saddr, const void* g) {
    asm volatile("cp.async.cg.shared.global [%0], [%1], 16;"
                 :: "r"(saddr), "l"(g) : "memory");
}
__device__ __forceinline__ void mma8(float* c, const uint32_t* a, const uint32_t* b) {
    asm volatile(
        "mma.sync.aligned.m16n8k8.row.col.f32.tf32.tf32.f32 "
        "{%0,%1,%2,%3}, {%4,%5,%6,%7}, {%8,%9}, {%0,%1,%2,%3};"
        : "+f"(c[0]), "+f"(c[1]), "+f"(c[2]), "+f"(c[3])
        : "r"(a[0]), "r"(a[1]), "r"(a[2]), "r"(a[3]), "r"(b[0]), "r"(b[1]));
}
__device__ __forceinline__ float silu_f(float h) {
    return h / (1.0f + expf(-h));
}

// ---------------- gating -----------------------------------------------------
__global__ __launch_bounds__(256) void gate_kernel(const float* __restrict__ x,
                                                   const float* __restrict__ Wg)
{
    __shared__ float xs[D_];
    __shared__ float red[8][E_];
    __shared__ float probs[E_];
    int t = blockIdx.x, tid = threadIdx.x;
    ((float4*)xs)[tid] = ((const float4*)(x + (size_t)t * D_))[tid];
    __syncthreads();
    int e = tid & 31, seg = tid >> 5, k0 = seg * (D_/8);
    float acc = 0.f;
    #pragma unroll 8
    for (int k = 0; k < D_/8; ++k)
        acc = fmaf(xs[k0 + k], Wg[(size_t)(k0 + k) * E_ + e], acc);
    red[seg][e] = acc;
    __syncthreads();
    if (tid < E_) {
        float s = 0.f;
        #pragma unroll
        for (int i = 0; i < 8; ++i) s += red[i][tid];
        float m = s;
        #pragma unroll
        for (int o = 16; o > 0; o >>= 1) m = fmaxf(m, __shfl_xor_sync(0xffffffffu, m, o));
        float p = expf(s - m);
        float sum = p;
        #pragma unroll
        for (int o = 16; o > 0; o >>= 1) sum += __shfl_xor_sync(0xffffffffu, sum, o);
        probs[tid] = p / sum;
    }
    __syncthreads();
    if (tid == 0) {
        bool used[E_];
        #pragma unroll
        for (int i = 0; i < E_; ++i) used[i] = false;
        for (int k = 0; k < TOPK_; ++k) {
            float best = -1.f; int bi = 0;
            for (int i = 0; i < E_; ++i)
                if (!used[i] && probs[i] > best) { best = probs[i]; bi = i; }
            used[bi] = true;
            g_topk_idx[t * TOPK_ + k] = bi;
            g_topk_w  [t * TOPK_ + k] = best;
        }
    }
}

__global__ void zero_counts_kernel() {
    if (threadIdx.x < E_) g_counts[threadIdx.x] = 0;
}

__global__ void dispatch_kernel() {
    int p = blockIdx.x * blockDim.x + threadIdx.x;
    if (p >= P_) return;
    int e   = g_topk_idx[p];
    int tok = p >> 2;
    int pos = atomicAdd(&g_counts[e], 1);
    if (pos < CAP_) {
        int slot = e * CAP_ + pos;
        g_rows_token[slot] = tok;
        g_slot_pair[slot]  = p;
        g_pair_wc[p]       = g_topk_w[p];
    } else {
        g_pair_wc[p] = 0.0f;
    }
}

// ---------------- unified tf32 mma.sync GEMM --------------------------------
// MODE 0: Gs   = silu(x@Ws1)*(x@Ws3)       A=[T,D]    B=[D,HS]   dual
// MODE 1: y    = Gs@Ws2                    A=[T,HS]   B=[HS,D]   single
// MODE 2: Gbuf = silu(gather(x)@W1)*( @W3) A=gather   B=[D,H]    dual
// MODE 3: Obuf = Gbuf@W2                   A=e-rows   B=[H,D]    single
//
// CTA tile 128x128, warp tile 64x32 (2x4 warps), K-chunk 32, 2-stage cp.async.
// A smem [128][36] (row-major M,K); B smem [32][136] (row-major K,N).
// Fragments rounded to tf32 (rna) in registers before each mma.
template<int MODE>
__global__ void __launch_bounds__(256, ((MODE==0||MODE==2) ? 1 : 2))
gemm_mma(const float* __restrict__ A,
         const float* __restrict__ B1,
         const float* __restrict__ B3,
         float* __restrict__ Out)
{
    constexpr bool DUAL   = (MODE == 0 || MODE == 2);
    constexpr bool EXPERT = (MODE >= 2);
    constexpr int  KLEN   = (MODE == 3) ? H_ : ((MODE == 1) ? HS_ : D_);
    constexpr int  NTOT   = (MODE == 0) ? HS_ : ((MODE == 2) ? H_ : D_);
    constexpr int  NCH    = KLEN / 32;
    constexpr int  AF     = 36;                 // A smem row stride (floats)
    constexpr int  BF     = 136;                // B smem row stride (floats)
    constexpr int  ABYTES = 128 * AF * 4;       // 18432
    constexpr int  BBYTES = 32 * BF * 4;        // 17408
    constexpr int  STAGE  = ABYTES + (DUAL ? 2 : 1) * BBYTES;

    extern __shared__ char smem[];
    const uint32_t sb0 = smem_u32(smem);

    const int tid  = threadIdx.x;
    const int wid  = tid >> 5, lane = tid & 31;
    const int e    = EXPERT ? blockIdx.z : 0;
    const int nc   = EXPERT ? min(g_counts[e], CAP_) : (1 << 30);
    const int r0   = blockIdx.y * 128;
    if (EXPERT && r0 >= nc) return;
    const int n0   = blockIdx.x * 128;

    // ---- per-thread cp.async source/dest addressing ----
    const int alr = tid >> 1, alc = (tid & 1) * 16;   // A: row, col-offset
    const float* asrc;
    if (MODE == 2) {
        int gr  = min(r0 + alr, nc - 1);
        int tok = g_rows_token[e * CAP_ + gr];
        asrc = A + (size_t)tok * D_ + alc;
    } else if (MODE == 3) {
        asrc = A + ((size_t)e * CAP_ + r0 + alr) * H_ + alc;
    } else {
        asrc = A + (size_t)(r0 + alr) * KLEN + alc;
    }
    const int bkr = tid >> 3, bcf = (tid & 7) * 16;   // B: k-row, n-offset
    const size_t eb = (MODE == 2) ? (size_t)e * D_ * H_
                    : ((MODE == 3) ? (size_t)e * H_ * D_ : 0);
    const float* b1src = B1 + eb + (size_t)bkr * NTOT + n0 + bcf;
    const float* b3src = DUAL ? (B3 + eb + (size_t)bkr * NTOT + n0 + bcf) : A;
    const uint32_t adst = (uint32_t)(alr * (AF * 4) + alc * 4);
    const uint32_t bdst = (uint32_t)(bkr * (BF * 4) + bcf * 4);

    // ---- accumulators ----
    float acc1[4][4][4];
    float acc3[4][4][4];
    #pragma unroll
    for (int i = 0; i < 4; ++i)
        #pragma unroll
        for (int j = 0; j < 4; ++j)
            #pragma unroll
            for (int k = 0; k < 4; ++k) { acc1[i][j][k] = 0.f; if (DUAL) acc3[i][j][k] = 0.f; }

    auto issue = [&](int c, int s) {
        uint32_t base = sb0 + (uint32_t)s * STAGE;
        const float* a = asrc + c * 32;
        #pragma unroll
        for (int j = 0; j < 4; ++j) cp16(base + adst + j * 16, a + j * 4);
        const float* b = b1src + (size_t)c * 32 * NTOT;
        #pragma unroll
        for (int j = 0; j < 4; ++j) cp16(base + ABYTES + bdst + j * 16, b + j * 4);
        if (DUAL) {
            const float* b3 = b3src + (size_t)c * 32 * NTOT;
            #pragma unroll
            for (int j = 0; j < 4; ++j) cp16(base + ABYTES + BBYTES + bdst + j * 16, b3 + j * 4);
        }
        asm volatile("cp.async.commit_group;" ::: "memory");
    };

    const int g = lane >> 2, q = lane & 3;
    const int wr = (wid >> 2) * 64, wc = (wid & 3) * 32;

    issue(0, 0);
    for (int c = 0; c < NCH; ++c) {
        int s = c & 1;
        if (c + 1 < NCH) {
            issue(c + 1, s ^ 1);
            asm volatile("cp.async.wait_group 1;" ::: "memory");
        } else {
            asm volatile("cp.async.wait_group 0;" ::: "memory");
        }
        __syncthreads();

        const float* As  = (const float*)(smem + (size_t)s * STAGE);
        const float* Bs1 = (const float*)(smem + (size_t)s * STAGE + ABYTES);
        const float* Bs3 = (const float*)(smem + (size_t)s * STAGE + ABYTES + BBYTES);

        #pragma unroll
        for (int ks = 0; ks < 4; ++ks) {
            const int kk = ks * 8;
            uint32_t af[4][4];
            #pragma unroll
            for (int mt = 0; mt < 4; ++mt) {
                const float* ap = As + (wr + 16 * mt + g) * AF + kk + q;
                af[mt][0] = rna_b(ap[0]);
                af[mt][1] = rna_b(ap[8 * AF]);
                af[mt][2] = rna_b(ap[4]);
                af[mt][3] = rna_b(ap[8 * AF + 4]);
            }
            uint32_t bf1[4][2];
            #pragma unroll
            for (int nt = 0; nt < 4; ++nt) {
                const float* bp = Bs1 + (kk + q) * BF + wc + 8 * nt + g;
                bf1[nt][0] = rna_b(bp[0]);
                bf1[nt][1] = rna_b(bp[4 * BF]);
            }
            #pragma unroll
            for (int mt = 0; mt < 4; ++mt)
                #pragma unroll
                for (int nt = 0; nt < 4; ++nt)
                    mma8(acc1[mt][nt], af[mt], bf1[nt]);
            if (DUAL) {
                uint32_t bf3[4][2];
                #pragma unroll
                for (int nt = 0; nt < 4; ++nt) {
                    const float* bp = Bs3 + (kk + q) * BF + wc + 8 * nt + g;
                    bf3[nt][0] = rna_b(bp[0]);
                    bf3[nt][1] = rna_b(bp[4 * BF]);
                }
                #pragma unroll
                for (int mt = 0; mt < 4; ++mt)
                    #pragma unroll
                    for (int nt = 0; nt < 4; ++nt)
                        mma8(acc3[mt][nt], af[mt], bf3[nt]);
            }
        }
        __syncthreads();
    }

    // ---- epilogue ----
    #pragma unroll
    for (int mt = 0; mt < 4; ++mt) {
        #pragma unroll
        for (int h = 0; h < 2; ++h) {
            const int grow = r0 + wr + 16 * mt + 8 * h + g;
            const bool valid = EXPERT ? (grow < nc) : true;
            if (!valid) continue;
            float* orow;
            if (MODE == 0)      orow = Out + (size_t)grow * HS_;
            else if (MODE == 1) orow = Out + (size_t)grow * D_;
            else if (MODE == 2) orow = Out + ((size_t)e * CAP_ + grow) * H_;
            else {
                int p = g_slot_pair[e * CAP_ + grow];
                orow = Out + (size_t)p * D_;
            }
            #pragma unroll
            for (int nt = 0; nt < 4; ++nt) {
                const int col = n0 + wc + 8 * nt + 2 * q;
                float v0 = acc1[mt][nt][2 * h];
                float v1 = acc1[mt][nt][2 * h + 1];
                if (DUAL) {
                    v0 = silu_f(v0) * acc3[mt][nt][2 * h];
                    v1 = silu_f(v1) * acc3[mt][nt][2 * h + 1];
                }
                float2 vv; vv.x = v0; vv.y = v1;
                *(float2*)(orow + col) = vv;
            }
        }
    }
}

// ---------------- combine: y = z + sum_k w_k * Obuf[pair] -------------------
__global__ __launch_bounds__(256) void combine_kernel(float* __restrict__ y)
{
    int t = blockIdx.x;
    int c4 = threadIdx.x;
    size_t off = (size_t)t * D_ + c4 * 4;
    float4 acc = *(float4*)(y + off);
    #pragma unroll
    for (int k = 0; k < TOPK_; ++k) {
        int p = t * TOPK_ + k;
        float w = g_pair_wc[p];
        float4 o = *(const float4*)(g_Obuf + (size_t)p * D_ + c4 * 4);
        acc.x = fmaf(w, o.x, acc.x);
        acc.y = fmaf(w, o.y, acc.y);
        acc.z = fmaf(w, o.z, acc.z);
        acc.w = fmaf(w, o.w, acc.w);
    }
    *(float4*)(y + off) = acc;
}

// ---------------- launch -----------------------------------------------------
extern "C" void kernel_launch(void* const* d_in, const int* in_sizes, int n_in,
                              void* d_out, int out_size)
{
    const float* x   = (const float*)d_in[0];
    const float* Wg  = (const float*)d_in[1];
    const float* W1  = (const float*)d_in[2];
    const float* W2  = (const float*)d_in[3];
    const float* W3  = (const float*)d_in[4];
    const float* Ws1 = (const float*)d_in[5];
    const float* Ws2 = (const float*)d_in[6];
    const float* Ws3 = (const float*)d_in[7];
    float* y = (float*)d_out;

    const int SMEM_DUAL   = 2 * (128*36*4 + 2 * 32*136*4);  // 106496
    const int SMEM_SINGLE = 2 * (128*36*4 + 1 * 32*136*4);  // 71680
    cudaFuncSetAttribute(gemm_mma<0>, cudaFuncAttributeMaxDynamicSharedMemorySize, SMEM_DUAL);
    cudaFuncSetAttribute(gemm_mma<1>, cudaFuncAttributeMaxDynamicSharedMemorySize, SMEM_SINGLE);
    cudaFuncSetAttribute(gemm_mma<2>, cudaFuncAttributeMaxDynamicSharedMemorySize, SMEM_DUAL);
    cudaFuncSetAttribute(gemm_mma<3>, cudaFuncAttributeMaxDynamicSharedMemorySize, SMEM_SINGLE);

    void *p_gs, *p_gbuf, *p_obuf;
    cudaGetSymbolAddress(&p_gs,   g_Gs);
    cudaGetSymbolAddress(&p_gbuf, g_Gbuf);
    cudaGetSymbolAddress(&p_obuf, g_Obuf);

    gate_kernel<<<T_, 256>>>(x, Wg);
    zero_counts_kernel<<<1, 32>>>();
    dispatch_kernel<<<P_/256, 256>>>();

    // shared expert (writes all of y via MODE 1)
    gemm_mma<0><<<dim3(HS_/128, T_/128), 256, SMEM_DUAL>>>(x, Ws1, Ws3, (float*)p_gs);
    gemm_mma<1><<<dim3(D_/128, T_/128), 256, SMEM_SINGLE>>>((const float*)p_gs, Ws2, nullptr, y);

    // routed experts
    gemm_mma<2><<<dim3(H_/128, CAP_/128, E_), 256, SMEM_DUAL>>>(x, W1, W3, (float*)p_gbuf);
    gemm_mma<3><<<dim3(D_/128, CAP_/128, E_), 256, SMEM_SINGLE>>>((const float*)p_gbuf, W2, nullptr, (float*)p_obuf);

    // deterministic combine
    combine_kernel<<<T_, 256>>>(y);
}

// round 6
// speedup vs baseline: 2.5052x; 1.1013x over previous
#include <cuda_runtime.h>
#include <math.h>
#include <stdint.h>

// Problem shapes (fixed by the dataset)
#define T_    4096
#define D_    1024
#define H_    512
#define E_    32
#define TOPK_ 4
#define CAP_  2048
#define HS_   1024
#define P_    (T_*TOPK_)

// ---------------- scratch (device globals) ----------------------------------
__device__ int   g_topk_idx[P_];
__device__ float g_topk_w[P_];
__device__ float g_pair_wc[P_];
__device__ int   g_counts[E_];
__device__ int   g_rows_token[E_*CAP_];
__device__ int   g_slot_pair[E_*CAP_];
__device__ __align__(256) float g_xr[(size_t)T_*D_];          // rna(x)
__device__ __align__(256) float g_W1r[(size_t)E_*D_*H_];
__device__ __align__(256) float g_W3r[(size_t)E_*D_*H_];
__device__ __align__(256) float g_W2r[(size_t)E_*H_*D_];
__device__ __align__(256) float g_Ws1r[(size_t)D_*HS_];
__device__ __align__(256) float g_Ws3r[(size_t)D_*HS_];
__device__ __align__(256) float g_Ws2r[(size_t)HS_*D_];
__device__ __align__(256) float g_Gs[(size_t)T_*HS_];         // shared hidden (rna)
__device__ __align__(256) float g_Gbuf[(size_t)E_*CAP_*H_];   // expert hidden (rna)
__device__ __align__(256) float g_Obuf[(size_t)P_*D_];        // per-pair outputs

// ---------------- helpers ----------------------------------------------------
__device__ __forceinline__ uint32_t smem_u32(const void* p) {
    uint32_t a;
    asm("{ .reg .u64 t; cvta.to.shared.u64 t, %1; cvt.u32.u64 %0, t; }"
        : "=r"(a) : "l"(p));
    return a;
}
__device__ __forceinline__ uint32_t rna_b(float v) {
    uint32_t o;
    asm("cvt.rna.tf32.f32 %0, %1;" : "=r"(o) : "f"(v));
    return o;
}
__device__ __forceinline__ float rna_f(float v) {
    return __uint_as_float(rna_b(v));
}
__device__ __forceinline__ void cp16(uint32_t saddr, const void* g) {
    asm volatile("cp.async.cg.shared.global [%0], [%1], 16;"
                 :: "r"(saddr), "l"(g) : "memory");
}
__device__ __forceinline__ void cp_commit() {
    asm volatile("cp.async.commit_group;" ::: "memory");
}
template<int N>
__device__ __forceinline__ void cp_wait() {
    asm volatile("cp.async.wait_group %0;" :: "n"(N) : "memory");
}
__device__ __forceinline__ void mma8(float* c, const uint32_t* a, const uint32_t* b) {
    asm volatile(
        "mma.sync.aligned.m16n8k8.row.col.f32.tf32.tf32.f32 "
        "{%0,%1,%2,%3}, {%4,%5,%6,%7}, {%8,%9}, {%0,%1,%2,%3};"
        : "+f"(c[0]), "+f"(c[1]), "+f"(c[2]), "+f"(c[3])
        : "r"(a[0]), "r"(a[1]), "r"(a[2]), "r"(a[3]), "r"(b[0]), "r"(b[1]));
}
__device__ __forceinline__ float silu_f(float h) {
    return h / (1.0f + expf(-h));
}

// ---------------- prepass: rna round-copy -----------------------------------
__global__ __launch_bounds__(256) void round_copy(const float4* __restrict__ src,
                                                  float4* __restrict__ dst, int n4)
{
    int i = blockIdx.x * 256 + threadIdx.x;
    if (i < n4) {
        float4 v = src[i];
        v.x = rna_f(v.x); v.y = rna_f(v.y); v.z = rna_f(v.z); v.w = rna_f(v.w);
        dst[i] = v;
    }
}

// ---------------- gating -----------------------------------------------------
__global__ __launch_bounds__(256) void gate_kernel(const float* __restrict__ x,
                                                   const float* __restrict__ Wg)
{
    __shared__ float xs[D_];
    __shared__ float red[8][E_];
    __shared__ float probs[E_];
    int t = blockIdx.x, tid = threadIdx.x;
    ((float4*)xs)[tid] = ((const float4*)(x + (size_t)t * D_))[tid];
    __syncthreads();
    int e = tid & 31, seg = tid >> 5, k0 = seg * (D_/8);
    float acc = 0.f;
    #pragma unroll 8
    for (int k = 0; k < D_/8; ++k)
        acc = fmaf(xs[k0 + k], Wg[(size_t)(k0 + k) * E_ + e], acc);
    red[seg][e] = acc;
    __syncthreads();
    if (tid < E_) {
        float s = 0.f;
        #pragma unroll
        for (int i = 0; i < 8; ++i) s += red[i][tid];
        float m = s;
        #pragma unroll
        for (int o = 16; o > 0; o >>= 1) m = fmaxf(m, __shfl_xor_sync(0xffffffffu, m, o));
        float p = expf(s - m);
        float sum = p;
        #pragma unroll
        for (int o = 16; o > 0; o >>= 1) sum += __shfl_xor_sync(0xffffffffu, sum, o);
        probs[tid] = p / sum;
    }
    __syncthreads();
    if (tid == 0) {
        bool used[E_];
        #pragma unroll
        for (int i = 0; i < E_; ++i) used[i] = false;
        for (int k = 0; k < TOPK_; ++k) {
            float best = -1.f; int bi = 0;
            for (int i = 0; i < E_; ++i)
                if (!used[i] && probs[i] > best) { best = probs[i]; bi = i; }
            used[bi] = true;
            g_topk_idx[t * TOPK_ + k] = bi;
            g_topk_w  [t * TOPK_ + k] = best;
        }
    }
}

__global__ void zero_counts_kernel() {
    if (threadIdx.x < E_) g_counts[threadIdx.x] = 0;
}

__global__ void dispatch_kernel() {
    int p = blockIdx.x * blockDim.x + threadIdx.x;
    if (p >= P_) return;
    int e   = g_topk_idx[p];
    int tok = p >> 2;
    int pos = atomicAdd(&g_counts[e], 1);
    if (pos < CAP_) {
        int slot = e * CAP_ + pos;
        g_rows_token[slot] = tok;
        g_slot_pair[slot]  = p;
        g_pair_wc[p]       = g_topk_w[p];
    } else {
        g_pair_wc[p] = 0.0f;
    }
}

// ---------------- unified tf32 mma.sync GEMM (512 threads, multistage) ------
// MODE 0: Gs   = rna(silu(x@Ws1)*(x@Ws3))   dual    MODE 1: y    = Gs@Ws2
// MODE 2: Gbuf = rna(silu(xg@W1)*(xg@W3))   dual    MODE 3: Obuf = Gbuf@W2
// CTA tile 128x128, 16 warps, uniform warp tile 32x32 (4x4 warp grid).
// K-chunk 32; stages: dual 3, single 4. One barrier per chunk.
// All operands pre-rounded to tf32 -> no in-loop cvt.
template<int MODE>
__global__ void __launch_bounds__(512, 1)
gemm_mma(const float* __restrict__ A,
         const float* __restrict__ B1,
         const float* __restrict__ B3,
         float* __restrict__ Out)
{
    constexpr bool DUAL   = (MODE == 0 || MODE == 2);
    constexpr bool EXPERT = (MODE >= 2);
    constexpr int  KLEN   = (MODE == 3) ? H_ : ((MODE == 1) ? HS_ : D_);
    constexpr int  NTOT   = (MODE == 0) ? HS_ : ((MODE == 2) ? H_ : D_);
    constexpr int  NCH    = KLEN / 32;
    constexpr int  S      = DUAL ? 3 : 4;            // pipeline stages
    constexpr int  NT     = 4;                       // n8 tiles per warp (32 cols)
    constexpr int  AF     = 36;
    constexpr int  BF     = 136;
    constexpr int  ABYTES = 128 * AF * 4;            // 18432
    constexpr int  BBYTES = 32 * BF * 4;             // 17408
    constexpr int  STAGE  = ABYTES + (DUAL ? 2 : 1) * BBYTES;

    extern __shared__ char smem[];
    const uint32_t sb0 = smem_u32(smem);

    const int tid = threadIdx.x;
    const int wid = tid >> 5, lane = tid & 31;
    const int e   = EXPERT ? blockIdx.z : 0;
    const int nc  = EXPERT ? min(g_counts[e], CAP_) : (1 << 30);
    const int r0  = blockIdx.y * 128;
    if (EXPERT && r0 >= nc) return;
    const int n0  = blockIdx.x * 128;

    // ---- cp.async addressing: A 4 thr/row x 2 cp16; B 16 thr/row x 2 cp16 --
    const int alr = tid >> 2, alc = (tid & 3) * 8;
    const float* asrc;
    if (MODE == 2) {
        int gr  = min(r0 + alr, nc - 1);
        int tok = g_rows_token[e * CAP_ + gr];
        asrc = A + (size_t)tok * D_ + alc;
    } else if (MODE == 3) {
        asrc = A + ((size_t)e * CAP_ + r0 + alr) * H_ + alc;
    } else {
        asrc = A + (size_t)(r0 + alr) * KLEN + alc;
    }
    const int bkr = tid >> 4, bcf = (tid & 15) * 8;
    const size_t eb = (MODE == 2) ? (size_t)e * D_ * H_
                    : ((MODE == 3) ? (size_t)e * H_ * D_ : 0);
    const float* b1src = B1 + eb + (size_t)bkr * NTOT + n0 + bcf;
    const float* b3src = DUAL ? (B3 + eb + (size_t)bkr * NTOT + n0 + bcf) : A;
    const uint32_t adst = (uint32_t)(alr * (AF * 4) + alc * 4);
    const uint32_t bdst = (uint32_t)(bkr * (BF * 4) + bcf * 4);

    auto issue = [&](int c, int s) {
        uint32_t base = sb0 + (uint32_t)s * STAGE;
        const float* a = asrc + c * 32;
        cp16(base + adst,      a);
        cp16(base + adst + 16, a + 4);
        const float* b = b1src + (size_t)c * 32 * NTOT;
        cp16(base + ABYTES + bdst,      b);
        cp16(base + ABYTES + bdst + 16, b + 4);
        if (DUAL) {
            const float* b3 = b3src + (size_t)c * 32 * NTOT;
            cp16(base + ABYTES + BBYTES + bdst,      b3);
            cp16(base + ABYTES + BBYTES + bdst + 16, b3 + 4);
        }
        cp_commit();
    };

    // ---- accumulators ----
    float acc1[2][NT][4];
    float acc3[DUAL ? 2 : 1][DUAL ? NT : 1][4];
    #pragma unroll
    for (int i = 0; i < 2; ++i)
        #pragma unroll
        for (int j = 0; j < NT; ++j)
            #pragma unroll
            for (int k = 0; k < 4; ++k) {
                acc1[i][j][k] = 0.f;
                if (DUAL) acc3[i][j][k] = 0.f;
            }

    const int g = lane >> 2, q = lane & 3;
    const int wr = (wid >> 2) * 32, wc = (wid & 3) * 32;   // 4x4 warp grid

    // ---- prologue: fill S-1 stages ----
    #pragma unroll
    for (int i = 0; i < S - 1; ++i) issue(i, i);
    cp_wait<S - 2>();
    __syncthreads();

    // ---- mainloop: one barrier per chunk ----
    for (int c = 0; c < NCH; ++c) {
        const int s = c % S;
        if (c + S - 1 < NCH) issue(c + S - 1, (c + S - 1) % S);

        const float* As  = (const float*)(smem + (size_t)s * STAGE);
        const float* Bs1 = (const float*)(smem + (size_t)s * STAGE + ABYTES);
        const float* Bs3 = (const float*)(smem + (size_t)s * STAGE + ABYTES + BBYTES);

        #pragma unroll
        for (int ks = 0; ks < 4; ++ks) {
            const int kk = ks * 8;
            uint32_t af[2][4];
            #pragma unroll
            for (int mt = 0; mt < 2; ++mt) {
                const float* ap = As + (wr + 16 * mt + g) * AF + kk + q;
                af[mt][0] = __float_as_uint(ap[0]);
                af[mt][1] = __float_as_uint(ap[8 * AF]);
                af[mt][2] = __float_as_uint(ap[4]);
                af[mt][3] = __float_as_uint(ap[8 * AF + 4]);
            }
            #pragma unroll
            for (int nt = 0; nt < NT; ++nt) {
                const float* bp = Bs1 + (kk + q) * BF + wc + 8 * nt + g;
                uint32_t bf[2];
                bf[0] = __float_as_uint(bp[0]);
                bf[1] = __float_as_uint(bp[4 * BF]);
                mma8(acc1[0][nt], af[0], bf);
                mma8(acc1[1][nt], af[1], bf);
                if (DUAL) {
                    const float* bp3 = Bs3 + (kk + q) * BF + wc + 8 * nt + g;
                    uint32_t bf3[2];
                    bf3[0] = __float_as_uint(bp3[0]);
                    bf3[1] = __float_as_uint(bp3[4 * BF]);
                    mma8(acc3[0][nt], af[0], bf3);
                    mma8(acc3[1][nt], af[1], bf3);
                }
            }
        }
        cp_wait<S - 2>();
        __syncthreads();
    }

    // ---- epilogue ----
    #pragma unroll
    for (int mt = 0; mt < 2; ++mt) {
        #pragma unroll
        for (int h = 0; h < 2; ++h) {
            const int grow = r0 + wr + 16 * mt + 8 * h + g;
            const bool valid = EXPERT ? (grow < nc) : true;
            if (!valid) continue;
            float* orow;
            if (MODE == 0)      orow = Out + (size_t)grow * HS_;
            else if (MODE == 1) orow = Out + (size_t)grow * D_;
            else if (MODE == 2) orow = Out + ((size_t)e * CAP_ + grow) * H_;
            else {
                int p = g_slot_pair[e * CAP_ + grow];
                orow = Out + (size_t)p * D_;
            }
            #pragma unroll
            for (int nt = 0; nt < NT; ++nt) {
                const int col = n0 + wc + 8 * nt + 2 * q;
                float v0 = acc1[mt][nt][2 * h];
                float v1 = acc1[mt][nt][2 * h + 1];
                if (DUAL) {
                    v0 = rna_f(silu_f(v0) * acc3[mt][nt][2 * h]);
                    v1 = rna_f(silu_f(v1) * acc3[mt][nt][2 * h + 1]);
                }
                float2 vv; vv.x = v0; vv.y = v1;
                *(float2*)(orow + col) = vv;
            }
        }
    }
}

// ---------------- combine: y = z + sum_k w_k * Obuf[pair] -------------------
__global__ __launch_bounds__(256) void combine_kernel(float* __restrict__ y)
{
    int t = blockIdx.x;
    int c4 = threadIdx.x;
    size_t off = (size_t)t * D_ + c4 * 4;
    float4 acc = *(float4*)(y + off);
    #pragma unroll
    for (int k = 0; k < TOPK_; ++k) {
        int p = t * TOPK_ + k;
        float w = g_pair_wc[p];
        float4 o = *(const float4*)(g_Obuf + (size_t)p * D_ + c4 * 4);
        acc.x = fmaf(w, o.x, acc.x);
        acc.y = fmaf(w, o.y, acc.y);
        acc.z = fmaf(w, o.z, acc.z);
        acc.w = fmaf(w, o.w, acc.w);
    }
    *(float4*)(y + off) = acc;
}

// ---------------- launch -----------------------------------------------------
extern "C" void kernel_launch(void* const* d_in, const int* in_sizes, int n_in,
                              void* d_out, int out_size)
{
    const float* x   = (const float*)d_in[0];
    const float* Wg  = (const float*)d_in[1];
    const float* W1  = (const float*)d_in[2];
    const float* W2  = (const float*)d_in[3];
    const float* W3  = (const float*)d_in[4];
    const float* Ws1 = (const float*)d_in[5];
    const float* Ws2 = (const float*)d_in[6];
    const float* Ws3 = (const float*)d_in[7];
    float* y = (float*)d_out;

    const int SMEM_DUAL   = 3 * (128*36*4 + 2 * 32*136*4);  // 159744
    const int SMEM_SINGLE = 4 * (128*36*4 + 1 * 32*136*4);  // 143360
    cudaFuncSetAttribute(gemm_mma<0>, cudaFuncAttributeMaxDynamicSharedMemorySize, SMEM_DUAL);
    cudaFuncSetAttribute(gemm_mma<1>, cudaFuncAttributeMaxDynamicSharedMemorySize, SMEM_SINGLE);
    cudaFuncSetAttribute(gemm_mma<2>, cudaFuncAttributeMaxDynamicSharedMemorySize, SMEM_DUAL);
    cudaFuncSetAttribute(gemm_mma<3>, cudaFuncAttributeMaxDynamicSharedMemorySize, SMEM_SINGLE);

    void *p_xr, *p_w1r, *p_w3r, *p_w2r, *p_ws1r, *p_ws3r, *p_ws2r;
    void *p_gs, *p_gbuf, *p_obuf;
    cudaGetSymbolAddress(&p_xr,   g_xr);
    cudaGetSymbolAddress(&p_w1r,  g_W1r);
    cudaGetSymbolAddress(&p_w3r,  g_W3r);
    cudaGetSymbolAddress(&p_w2r,  g_W2r);
    cudaGetSymbolAddress(&p_ws1r, g_Ws1r);
    cudaGetSymbolAddress(&p_ws3r, g_Ws3r);
    cudaGetSymbolAddress(&p_ws2r, g_Ws2r);
    cudaGetSymbolAddress(&p_gs,   g_Gs);
    cudaGetSymbolAddress(&p_gbuf, g_Gbuf);
    cudaGetSymbolAddress(&p_obuf, g_Obuf);

    // gating + dispatch
    gate_kernel<<<T_, 256>>>(x, Wg);
    zero_counts_kernel<<<1, 32>>>();
    dispatch_kernel<<<P_/256, 256>>>();

    // prepass: rna-round all GEMM operands (removes in-loop cvts)
    const int n4_x  = T_*D_/4,  n4_w = E_*D_*H_/4, n4_ws = D_*HS_/4;
    round_copy<<<(n4_x  + 255)/256, 256>>>((const float4*)x,   (float4*)p_xr,   n4_x);
    round_copy<<<(n4_w  + 255)/256, 256>>>((const float4*)W1,  (float4*)p_w1r,  n4_w);
    round_copy<<<(n4_w  + 255)/256, 256>>>((const float4*)W3,  (float4*)p_w3r,  n4_w);
    round_copy<<<(n4_w  + 255)/256, 256>>>((const float4*)W2,  (float4*)p_w2r,  n4_w);
    round_copy<<<(n4_ws + 255)/256, 256>>>((const float4*)Ws1, (float4*)p_ws1r, n4_ws);
    round_copy<<<(n4_ws + 255)/256, 256>>>((const float4*)Ws3, (float4*)p_ws3r, n4_ws);
    round_copy<<<(n4_ws + 255)/256, 256>>>((const float4*)Ws2, (float4*)p_ws2r, n4_ws);

    // shared expert (writes all of y via MODE 1)
    gemm_mma<0><<<dim3(HS_/128, T_/128), 512, SMEM_DUAL>>>(
        (const float*)p_xr, (const float*)p_ws1r, (const float*)p_ws3r, (float*)p_gs);
    gemm_mma<1><<<dim3(D_/128, T_/128), 512, SMEM_SINGLE>>>(
        (const float*)p_gs, (const float*)p_ws2r, nullptr, y);

    // routed experts
    gemm_mma<2><<<dim3(H_/128, CAP_/128, E_), 512, SMEM_DUAL>>>(
        (const float*)p_xr, (const float*)p_w1r, (const float*)p_w3r, (float*)p_gbuf);
    gemm_mma<3><<<dim3(D_/128, CAP_/128, E_), 512, SMEM_SINGLE>>>(
        (const float*)p_gbuf, (const float*)p_w2r, nullptr, (float*)p_obuf);

    // deterministic combine
    combine_kernel<<<T_, 256>>>(y);
}

// round 8
// speedup vs baseline: 2.5978x; 1.0369x over previous
#include <cuda_runtime.h>
#include <math.h>
#include <stdint.h>

// Problem shapes (fixed by the dataset)
#define T_    4096
#define D_    1024
#define H_    512
#define E_    32
#define TOPK_ 4
#define CAP_  2048
#define HS_   1024
#define P_    (T_*TOPK_)

// ---------------- scratch (device globals) ----------------------------------
__device__ int   g_topk_idx[P_];
__device__ float g_topk_w[P_];
__device__ float g_pair_wc[P_];
__device__ int   g_counts[E_];
__device__ int   g_rows_token[E_*CAP_];
__device__ int   g_slot_pair[E_*CAP_];
__device__ __align__(256) float g_xr[(size_t)T_*D_];          // rna(x)
__device__ __align__(256) float g_Gs[(size_t)T_*HS_];         // shared hidden (rna)
__device__ __align__(256) float g_Gbuf[(size_t)E_*CAP_*H_];   // expert hidden (rna)
__device__ __align__(256) float g_Obuf[(size_t)P_*D_];        // per-pair outputs

// ---------------- helpers ----------------------------------------------------
__device__ __forceinline__ uint32_t smem_u32(const void* p) {
    uint32_t a;
    asm("{ .reg .u64 t; cvta.to.shared.u64 t, %1; cvt.u32.u64 %0, t; }"
        : "=r"(a) : "l"(p));
    return a;
}
__device__ __forceinline__ uint32_t rna_b(float v) {
    uint32_t o;
    asm("cvt.rna.tf32.f32 %0, %1;" : "=r"(o) : "f"(v));
    return o;
}
__device__ __forceinline__ float rna_f(float v) {
    return __uint_as_float(rna_b(v));
}
__device__ __forceinline__ void cp16(uint32_t saddr, const void* g) {
    asm volatile("cp.async.cg.shared.global [%0], [%1], 16;"
                 :: "r"(saddr), "l"(g) : "memory");
}
__device__ __forceinline__ void cp_commit() {
    asm volatile("cp.async.commit_group;" ::: "memory");
}
template<int N>
__device__ __forceinline__ void cp_wait() {
    asm volatile("cp.async.wait_group %0;" :: "n"(N) : "memory");
}
__device__ __forceinline__ void mma8(float* c, const uint32_t* a, const uint32_t* b) {
    asm volatile(
        "mma.sync.aligned.m16n8k8.row.col.f32.tf32.tf32.f32 "
        "{%0,%1,%2,%3}, {%4,%5,%6,%7}, {%8,%9}, {%0,%1,%2,%3};"
        : "+f"(c[0]), "+f"(c[1]), "+f"(c[2]), "+f"(c[3])
        : "r"(a[0]), "r"(a[1]), "r"(a[2]), "r"(a[3]), "r"(b[0]), "r"(b[1]));
}
__device__ __forceinline__ float silu_f(float h) {
    return h / (1.0f + expf(-h));
}

// ---------------- prepass: rna round-copy (x only; cheap) -------------------
__global__ __launch_bounds__(256) void round_copy(const float4* __restrict__ src,
                                                  float4* __restrict__ dst, int n4)
{
    int i = blockIdx.x * 256 + threadIdx.x;
    if (i < n4) {
        float4 v = src[i];
        v.x = rna_f(v.x); v.y = rna_f(v.y); v.z = rna_f(v.z); v.w = rna_f(v.w);
        dst[i] = v;
    }
}

// ---------------- gating -----------------------------------------------------
__global__ __launch_bounds__(256) void gate_kernel(const float* __restrict__ x,
                                                   const float* __restrict__ Wg)
{
    __shared__ float xs[D_];
    __shared__ float red[8][E_];
    __shared__ float probs[E_];
    int t = blockIdx.x, tid = threadIdx.x;
    ((float4*)xs)[tid] = ((const float4*)(x + (size_t)t * D_))[tid];
    __syncthreads();
    int e = tid & 31, seg = tid >> 5, k0 = seg * (D_/8);
    float acc = 0.f;
    #pragma unroll 8
    for (int k = 0; k < D_/8; ++k)
        acc = fmaf(xs[k0 + k], Wg[(size_t)(k0 + k) * E_ + e], acc);
    red[seg][e] = acc;
    __syncthreads();
    if (tid < E_) {
        float s = 0.f;
        #pragma unroll
        for (int i = 0; i < 8; ++i) s += red[i][tid];
        float m = s;
        #pragma unroll
        for (int o = 16; o > 0; o >>= 1) m = fmaxf(m, __shfl_xor_sync(0xffffffffu, m, o));
        float p = expf(s - m);
        float sum = p;
        #pragma unroll
        for (int o = 16; o > 0; o >>= 1) sum += __shfl_xor_sync(0xffffffffu, sum, o);
        probs[tid] = p / sum;
    }
    __syncthreads();
    if (tid == 0) {
        bool used[E_];
        #pragma unroll
        for (int i = 0; i < E_; ++i) used[i] = false;
        for (int k = 0; k < TOPK_; ++k) {
            float best = -1.f; int bi = 0;
            for (int i = 0; i < E_; ++i)
                if (!used[i] && probs[i] > best) { best = probs[i]; bi = i; }
            used[bi] = true;
            g_topk_idx[t * TOPK_ + k] = bi;
            g_topk_w  [t * TOPK_ + k] = best;
        }
    }
}

__global__ void zero_counts_kernel() {
    if (threadIdx.x < E_) g_counts[threadIdx.x] = 0;
}

__global__ void dispatch_kernel() {
    int p = blockIdx.x * blockDim.x + threadIdx.x;
    if (p >= P_) return;
    int e   = g_topk_idx[p];
    int tok = p >> 2;
    int pos = atomicAdd(&g_counts[e], 1);
    if (pos < CAP_) {
        int slot = e * CAP_ + pos;
        g_rows_token[slot] = tok;
        g_slot_pair[slot]  = p;
        g_pair_wc[p]       = g_topk_w[p];
    } else {
        g_pair_wc[p] = 0.0f;
    }
}

// ---------------- unified tf32 mma.sync GEMM (512 threads, multistage) ------
// MODE 0: Gs   = rna(silu(x@Ws1)*(x@Ws3))   dual    MODE 1: y    = Gs@Ws2
// MODE 2: Gbuf = rna(silu(xg@W1)*(xg@W3))   dual    MODE 3: Obuf = Gbuf@W2
// CTA tile 128x128, 16 warps, uniform warp tile 32x32 (4x4 warp grid).
// K-chunk 32; stages: dual 3, single 4. One barrier per chunk.
// A operands are pre-rounded tf32 (x prepass / producer epilogue); B (weights)
// are read raw and rounded in-register per fragment (rna) -> no weight prepass.
template<int MODE>
__global__ void __launch_bounds__(512, 1)
gemm_mma(const float* __restrict__ A,
         const float* __restrict__ B1,
         const float* __restrict__ B3,
         float* __restrict__ Out)
{
    constexpr bool DUAL   = (MODE == 0 || MODE == 2);
    constexpr bool EXPERT = (MODE >= 2);
    constexpr int  KLEN   = (MODE == 3) ? H_ : ((MODE == 1) ? HS_ : D_);
    constexpr int  NTOT   = (MODE == 0) ? HS_ : ((MODE == 2) ? H_ : D_);
    constexpr int  NCH    = KLEN / 32;
    constexpr int  S      = DUAL ? 3 : 4;            // pipeline stages
    constexpr int  NT     = 4;                       // n8 tiles per warp (32 cols)
    constexpr int  AF     = 36;
    constexpr int  BF     = 136;
    constexpr int  ABYTES = 128 * AF * 4;            // 18432
    constexpr int  BBYTES = 32 * BF * 4;             // 17408
    constexpr int  STAGE  = ABYTES + (DUAL ? 2 : 1) * BBYTES;

    extern __shared__ char smem[];
    const uint32_t sb0 = smem_u32(smem);

    const int tid = threadIdx.x;
    const int wid = tid >> 5, lane = tid & 31;
    const int e   = EXPERT ? blockIdx.z : 0;
    const int nc  = EXPERT ? min(g_counts[e], CAP_) : (1 << 30);
    const int r0  = blockIdx.y * 128;
    if (EXPERT && r0 >= nc) return;
    const int n0  = blockIdx.x * 128;

    // ---- cp.async addressing: A 4 thr/row x 2 cp16; B 16 thr/row x 2 cp16 --
    const int alr = tid >> 2, alc = (tid & 3) * 8;
    const float* asrc;
    if (MODE == 2) {
        int gr  = min(r0 + alr, nc - 1);
        int tok = g_rows_token[e * CAP_ + gr];
        asrc = A + (size_t)tok * D_ + alc;
    } else if (MODE == 3) {
        asrc = A + ((size_t)e * CAP_ + r0 + alr) * H_ + alc;
    } else {
        asrc = A + (size_t)(r0 + alr) * KLEN + alc;
    }
    const int bkr = tid >> 4, bcf = (tid & 15) * 8;
    const size_t eb = (MODE == 2) ? (size_t)e * D_ * H_
                    : ((MODE == 3) ? (size_t)e * H_ * D_ : 0);
    const float* b1src = B1 + eb + (size_t)bkr * NTOT + n0 + bcf;
    const float* b3src = DUAL ? (B3 + eb + (size_t)bkr * NTOT + n0 + bcf) : A;
    const uint32_t adst = (uint32_t)(alr * (AF * 4) + alc * 4);
    const uint32_t bdst = (uint32_t)(bkr * (BF * 4) + bcf * 4);

    auto issue = [&](int c, int s) {
        uint32_t base = sb0 + (uint32_t)s * STAGE;
        const float* a = asrc + c * 32;
        cp16(base + adst,      a);
        cp16(base + adst + 16, a + 4);
        const float* b = b1src + (size_t)c * 32 * NTOT;
        cp16(base + ABYTES + bdst,      b);
        cp16(base + ABYTES + bdst + 16, b + 4);
        if (DUAL) {
            const float* b3 = b3src + (size_t)c * 32 * NTOT;
            cp16(base + ABYTES + BBYTES + bdst,      b3);
            cp16(base + ABYTES + BBYTES + bdst + 16, b3 + 4);
        }
        cp_commit();
    };

    // ---- accumulators ----
    float acc1[2][NT][4];
    float acc3[DUAL ? 2 : 1][DUAL ? NT : 1][4];
    #pragma unroll
    for (int i = 0; i < 2; ++i)
        #pragma unroll
        for (int j = 0; j < NT; ++j)
            #pragma unroll
            for (int k = 0; k < 4; ++k) {
                acc1[i][j][k] = 0.f;
                if (DUAL) acc3[i][j][k] = 0.f;
            }

    const int g = lane >> 2, q = lane & 3;
    const int wr = (wid >> 2) * 32, wc = (wid & 3) * 32;   // 4x4 warp grid

    // ---- prologue: fill S-1 stages ----
    #pragma unroll
    for (int i = 0; i < S - 1; ++i) issue(i, i);
    cp_wait<S - 2>();
    __syncthreads();

    // ---- mainloop: one barrier per chunk ----
    for (int c = 0; c < NCH; ++c) {
        const int s = c % S;
        if (c + S - 1 < NCH) issue(c + S - 1, (c + S - 1) % S);

        const float* As  = (const float*)(smem + (size_t)s * STAGE);
        const float* Bs1 = (const float*)(smem + (size_t)s * STAGE + ABYTES);
        const float* Bs3 = (const float*)(smem + (size_t)s * STAGE + ABYTES + BBYTES);

        #pragma unroll
        for (int ks = 0; ks < 4; ++ks) {
            const int kk = ks * 8;
            uint32_t af[2][4];
            #pragma unroll
            for (int mt = 0; mt < 2; ++mt) {
                const float* ap = As + (wr + 16 * mt + g) * AF + kk + q;
                af[mt][0] = __float_as_uint(ap[0]);
                af[mt][1] = __float_as_uint(ap[8 * AF]);
                af[mt][2] = __float_as_uint(ap[4]);
                af[mt][3] = __float_as_uint(ap[8 * AF + 4]);
            }
            #pragma unroll
            for (int nt = 0; nt < NT; ++nt) {
                const float* bp = Bs1 + (kk + q) * BF + wc + 8 * nt + g;
                uint32_t bf[2];
                bf[0] = rna_b(bp[0]);
                bf[1] = rna_b(bp[4 * BF]);
                mma8(acc1[0][nt], af[0], bf);
                mma8(acc1[1][nt], af[1], bf);
                if (DUAL) {
                    const float* bp3 = Bs3 + (kk + q) * BF + wc + 8 * nt + g;
                    uint32_t bf3[2];
                    bf3[0] = rna_b(bp3[0]);
                    bf3[1] = rna_b(bp3[4 * BF]);
                    mma8(acc3[0][nt], af[0], bf3);
                    mma8(acc3[1][nt], af[1], bf3);
                }
            }
        }
        cp_wait<S - 2>();
        __syncthreads();
    }

    // ---- epilogue ----
    #pragma unroll
    for (int mt = 0; mt < 2; ++mt) {
        #pragma unroll
        for (int h = 0; h < 2; ++h) {
            const int grow = r0 + wr + 16 * mt + 8 * h + g;
            const bool valid = EXPERT ? (grow < nc) : true;
            if (!valid) continue;
            float* orow;
            if (MODE == 0)      orow = Out + (size_t)grow * HS_;
            else if (MODE == 1) orow = Out + (size_t)grow * D_;
            else if (MODE == 2) orow = Out + ((size_t)e * CAP_ + grow) * H_;
            else {
                int p = g_slot_pair[e * CAP_ + grow];
                orow = Out + (size_t)p * D_;
            }
            #pragma unroll
            for (int nt = 0; nt < NT; ++nt) {
                const int col = n0 + wc + 8 * nt + 2 * q;
                float v0 = acc1[mt][nt][2 * h];
                float v1 = acc1[mt][nt][2 * h + 1];
                if (DUAL) {
                    v0 = rna_f(silu_f(v0) * acc3[mt][nt][2 * h]);
                    v1 = rna_f(silu_f(v1) * acc3[mt][nt][2 * h + 1]);
                }
                float2 vv; vv.x = v0; vv.y = v1;
                *(float2*)(orow + col) = vv;
            }
        }
    }
}

// ---------------- combine: y = z + sum_k w_k * Obuf[pair] -------------------
__global__ __launch_bounds__(256) void combine_kernel(float* __restrict__ y)
{
    int t = blockIdx.x;
    int c4 = threadIdx.x;
    size_t off = (size_t)t * D_ + c4 * 4;
    float4 acc = *(float4*)(y + off);
    #pragma unroll
    for (int k = 0; k < TOPK_; ++k) {
        int p = t * TOPK_ + k;
        float w = g_pair_wc[p];
        float4 o = *(const float4*)(g_Obuf + (size_t)p * D_ + c4 * 4);
        acc.x = fmaf(w, o.x, acc.x);
        acc.y = fmaf(w, o.y, acc.y);
        acc.z = fmaf(w, o.z, acc.z);
        acc.w = fmaf(w, o.w, acc.w);
    }
    *(float4*)(y + off) = acc;
}

// ---------------- launch -----------------------------------------------------
extern "C" void kernel_launch(void* const* d_in, const int* in_sizes, int n_in,
                              void* d_out, int out_size)
{
    const float* x   = (const float*)d_in[0];
    const float* Wg  = (const float*)d_in[1];
    const float* W1  = (const float*)d_in[2];
    const float* W2  = (const float*)d_in[3];
    const float* W3  = (const float*)d_in[4];
    const float* Ws1 = (const float*)d_in[5];
    const float* Ws2 = (const float*)d_in[6];
    const float* Ws3 = (const float*)d_in[7];
    float* y = (float*)d_out;

    const int SMEM_DUAL   = 3 * (128*36*4 + 2 * 32*136*4);  // 159744
    const int SMEM_SINGLE = 4 * (128*36*4 + 1 * 32*136*4);  // 143360
    cudaFuncSetAttribute(gemm_mma<0>, cudaFuncAttributeMaxDynamicSharedMemorySize, SMEM_DUAL);
    cudaFuncSetAttribute(gemm_mma<1>, cudaFuncAttributeMaxDynamicSharedMemorySize, SMEM_SINGLE);
    cudaFuncSetAttribute(gemm_mma<2>, cudaFuncAttributeMaxDynamicSharedMemorySize, SMEM_DUAL);
    cudaFuncSetAttribute(gemm_mma<3>, cudaFuncAttributeMaxDynamicSharedMemorySize, SMEM_SINGLE);

    void *p_xr, *p_gs, *p_gbuf, *p_obuf;
    cudaGetSymbolAddress(&p_xr,   g_xr);
    cudaGetSymbolAddress(&p_gs,   g_Gs);
    cudaGetSymbolAddress(&p_gbuf, g_Gbuf);
    cudaGetSymbolAddress(&p_obuf, g_Obuf);

    // gating + dispatch
    gate_kernel<<<T_, 256>>>(x, Wg);
    zero_counts_kernel<<<1, 32>>>();
    dispatch_kernel<<<P_/256, 256>>>();

    // prepass: rna-round x only (16 MB; ~8us). Weights are rounded in-register.
    const int n4_x = T_*D_/4;
    round_copy<<<(n4_x + 255)/256, 256>>>((const float4*)x, (float4*)p_xr, n4_x);

    // shared expert (writes all of y via MODE 1)
    gemm_mma<0><<<dim3(HS_/128, T_/128), 512, SMEM_DUAL>>>(
        (const float*)p_xr, Ws1, Ws3, (float*)p_gs);
    gemm_mma<1><<<dim3(D_/128, T_/128), 512, SMEM_SINGLE>>>(
        (const float*)p_gs, Ws2, nullptr, y);

    // routed experts
    gemm_mma<2><<<dim3(H_/128, CAP_/128, E_), 512, SMEM_DUAL>>>(
        (const float*)p_xr, W1, W3, (float*)p_gbuf);
    gemm_mma<3><<<dim3(D_/128, CAP_/128, E_), 512, SMEM_SINGLE>>>(
        (const float*)p_gbuf, W2, nullptr, (float*)p_obuf);

    // deterministic combine
    combine_kernel<<<T_, 256>>>(y);
}